// round 5
// baseline (speedup 1.0000x reference)
#include <cuda_runtime.h>
#include <cstdint>
#include <math.h>

// Problem constants: B=8, T=2048, D=2048, K=64
#define NROWS 16384   // B*T
#define DDIM  2048
#define KDIM  64

// Scratch (allocation-free: __device__ globals)
__device__ float g_pT[KDIM * DDIM];   // softmax(w) transposed: pT[k][d]
__device__ float g_nT[KDIM * DDIM];   // (w[:,k]-min_k)/(max_k-min_k) transposed
__device__ int   g_e[NROWS];          // per token: argmax k (bits 0..5) | neg-sign (bit 6)

// ---------------------------------------------------------------------------
// Kernel 1a: row softmax of w [D,K] over K, write transposed into g_pT.
// One warp per d-row (2 k per lane). exp/sum in fp64 so p matches true fp32
// values to <1 ulp (argmax robustness).
// ---------------------------------------------------------------------------
__global__ void prep_softmax(const float* __restrict__ w) {
    int gw = (blockIdx.x * blockDim.x + threadIdx.x) >> 5;  // d-row
    if (gw >= DDIM) return;
    int lane = threadIdx.x & 31;
    float w0 = w[gw * KDIM + lane];
    float w1 = w[gw * KDIM + lane + 32];
    float m = fmaxf(w0, w1);
#pragma unroll
    for (int off = 16; off; off >>= 1)
        m = fmaxf(m, __shfl_xor_sync(0xffffffffu, m, off));
    double e0 = exp((double)(w0 - m));
    double e1 = exp((double)(w1 - m));
    double s = e0 + e1;
#pragma unroll
    for (int off = 16; off; off >>= 1)
        s += __shfl_xor_sync(0xffffffffu, s, off);
    g_pT[lane * DDIM + gw]        = (float)(e0 / s);
    g_pT[(lane + 32) * DDIM + gw] = (float)(e1 / s);
}

// ---------------------------------------------------------------------------
// Kernel 1b: per-column min/max of w and normalized columns into g_nT[k][d].
// One CTA per k.
// ---------------------------------------------------------------------------
__global__ void prep_norm(const float* __restrict__ w) {
    const int k = blockIdx.x;
    const int tid = threadIdx.x;
    float mn = 3.402823466e38f, mx = -3.402823466e38f;
    for (int d = tid; d < DDIM; d += 256) {
        float v = w[d * KDIM + k];
        mn = fminf(mn, v);
        mx = fmaxf(mx, v);
    }
    __shared__ float smn[256], smx[256];
    smn[tid] = mn; smx[tid] = mx;
    __syncthreads();
    for (int s = 128; s; s >>= 1) {
        if (tid < s) {
            smn[tid] = fminf(smn[tid], smn[tid + s]);
            smx[tid] = fmaxf(smx[tid], smx[tid + s]);
        }
        __syncthreads();
    }
    mn = smn[0]; mx = smx[0];
    float inv = 1.f / (mx - mn);
    for (int d = tid; d < DDIM; d += 256)
        g_nT[k * DDIM + d] = (w[d * KDIM + k] - mn) * inv;
}

// ---------------------------------------------------------------------------
// Kernel 2: scores = x @ p (M=16384, Kred=2048, N=64) + per-row argmax/sign.
// Tile: 128 tokens x 64 k per CTA (128 CTAs), 256 threads.
// fma.rn.f32x2 with d-pairing: both operands are natural LDS.64 along d,
// accumulator holds (even-d, odd-d) partials per (tok,k). No pack/dup instrs.
// ---------------------------------------------------------------------------
#define TM 128
#define DC 16
#define XS 20   // smem row stride in words: conflict-free & 16B aligned

__device__ __forceinline__ void cp16(float* dst, const float* src) {
    unsigned s = (unsigned)__cvta_generic_to_shared(dst);
    asm volatile("cp.async.cg.shared.global [%0], [%1], 16;\n" :: "r"(s), "l"(src));
}

__global__ __launch_bounds__(256) void score_kernel(const float* __restrict__ x) {
    __shared__ float xs[2][TM * XS];     // xs[tok][d-chunk]
    __shared__ float ps[2][KDIM * XS];   // ps[k][d-chunk]
    const int tid = threadIdx.x;
    const long rowBase = (long)blockIdx.x * TM;
    const float* xg = x + rowBase * DDIM;
    const int kg = tid & 7;        // 8 k-groups
    const int tg = tid >> 3;       // 32 token-groups
    const int f4 = tid & 3;
    const int t4 = tid >> 2;       // 0..63

    unsigned long long acc[4][8];
#pragma unroll
    for (int i = 0; i < 4; i++)
#pragma unroll
        for (int j = 0; j < 8; j++) acc[i][j] = 0ull;

    auto fill = [&](int b, int c) {
        const int base = c * DC;
        cp16(&xs[b][t4 * XS + f4 * 4],        xg + (long)t4 * DDIM + base + f4 * 4);
        cp16(&xs[b][(t4 + 64) * XS + f4 * 4], xg + (long)(t4 + 64) * DDIM + base + f4 * 4);
        cp16(&ps[b][t4 * XS + f4 * 4],        g_pT + t4 * DDIM + base + f4 * 4);
        asm volatile("cp.async.commit_group;\n");
    };

    fill(0, 0);
#pragma unroll 1
    for (int c = 0; c < DDIM / DC; ++c) {
        const int b = c & 1;
        if (c + 1 < DDIM / DC) {
            fill(b ^ 1, c + 1);
            asm volatile("cp.async.wait_group 1;\n");
        } else {
            asm volatile("cp.async.wait_group 0;\n");
        }
        __syncthreads();
        const float* xb = xs[b];
        const float* pb = ps[b];
#pragma unroll
        for (int dp = 0; dp < DC / 2; ++dp) {
            unsigned long long xp[4], pp[8];
#pragma unroll
            for (int i = 0; i < 4; i++)
                xp[i] = *reinterpret_cast<const unsigned long long*>(xb + (tg + 32 * i) * XS + 2 * dp);
#pragma unroll
            for (int j = 0; j < 8; j++)
                pp[j] = *reinterpret_cast<const unsigned long long*>(pb + (kg + 8 * j) * XS + 2 * dp);
#pragma unroll
            for (int i = 0; i < 4; i++)
#pragma unroll
                for (int j = 0; j < 8; j++)
                    asm volatile("fma.rn.f32x2 %0, %1, %2, %0;"
                                 : "+l"(acc[i][j]) : "l"(xp[i]), "l"(pp[j]));
        }
        __syncthreads();
    }

    // Epilogue: per-token argmax over 64 k (8 local + shfl over 8 kg lanes).
    // Tie-break = smaller k (matches jnp.argmax first-index semantics).
    float bestv[4]; int bestk[4];
#pragma unroll
    for (int i = 0; i < 4; i++) {
        bestv[i] = -3.402823466e38f; bestk[i] = 0;
#pragma unroll
        for (int j = 0; j < 8; j++) {
            float lo = __uint_as_float((unsigned)(acc[i][j] & 0xffffffffull));
            float hi = __uint_as_float((unsigned)(acc[i][j] >> 32));
            float s = lo + hi;
            int k = kg + 8 * j;   // ascending in j => strict '>' keeps first max
            if (s > bestv[i]) { bestv[i] = s; bestk[i] = k; }
        }
    }
#pragma unroll
    for (int off = 4; off; off >>= 1) {
#pragma unroll
        for (int i = 0; i < 4; i++) {
            float ov = __shfl_down_sync(0xffffffffu, bestv[i], off, 8);
            int   ok = __shfl_down_sync(0xffffffffu, bestk[i], off, 8);
            if (ov > bestv[i] || (ov == bestv[i] && ok < bestk[i])) {
                bestv[i] = ov; bestk[i] = ok;
            }
        }
    }
    if (kg == 0) {
#pragma unroll
        for (int i = 0; i < 4; i++)
            g_e[rowBase + tg + 32 * i] = bestk[i] | (bestv[i] < 0.f ? 64 : 0);
    }
}

// ---------------------------------------------------------------------------
// Kernel 3: out[row] = x[row] * (1 + W), W from (k*, sign) of row-1 (same b).
// t==0 rows: out = x. One CTA per token row, float4 streaming.
// ---------------------------------------------------------------------------
__global__ __launch_bounds__(256) void out_kernel(const float* __restrict__ x,
                                                  float* __restrict__ out) {
    const long row = blockIdx.x;
    const int tid = threadIdx.x;
    const float4* xr = reinterpret_cast<const float4*>(x + row * DDIM);
    float4* orow = reinterpret_cast<float4*>(out + row * DDIM);
    if ((row & 2047) == 0) {          // t == 0 -> W = 0
        orow[tid] = xr[tid];
        orow[tid + 256] = xr[tid + 256];
        return;
    }
    const int e = g_e[row - 1];
    const float4* nr = reinterpret_cast<const float4*>(g_nT + (long)(e & 63) * DDIM);
    const bool neg = (e & 64) != 0;
#pragma unroll
    for (int it = 0; it < 2; ++it) {
        int i = tid + 256 * it;
        float4 xv = xr[i];
        float4 nv = nr[i];
        float wx = neg ? 1.f - nv.x : nv.x;
        float wy = neg ? 1.f - nv.y : nv.y;
        float wz = neg ? 1.f - nv.z : nv.z;
        float ww = neg ? 1.f - nv.w : nv.w;
        float4 o;
        o.x = fmaf(xv.x, wx, xv.x);   // x + x*W, matching reference ordering
        o.y = fmaf(xv.y, wy, xv.y);
        o.z = fmaf(xv.z, wz, xv.z);
        o.w = fmaf(xv.w, ww, xv.w);
        orow[i] = o;
    }
}

// ---------------------------------------------------------------------------
extern "C" void kernel_launch(void* const* d_in, const int* in_sizes, int n_in,
                              void* d_out, int out_size) {
    const float* x = (const float*)d_in[0];   // [8,2048,2048]
    const float* w = (const float*)d_in[1];   // [2048,64]
    if (n_in >= 2 && in_sizes[0] < in_sizes[1]) {  // defensive: x is the big one
        const float* t = x; x = w; w = t;
    }
    prep_softmax<<<DDIM / 8, 256>>>(w);          // 8 warp-rows per CTA
    prep_norm<<<KDIM, 256>>>(w);
    score_kernel<<<NROWS / TM, 256>>>(x);
    out_kernel<<<NROWS, 256>>>(x, (float*)d_out);
}

// round 8
// speedup vs baseline: 1.1973x; 1.1973x over previous
#include <cuda_runtime.h>
#include <cstdint>
#include <math.h>

// Problem constants: B=8, T=2048, D=2048, K=64
#define NROWS 16384
#define DDIM  2048
#define KDIM  64

// Scratch (allocation-free __device__ globals)
__device__ float2 g_pP[KDIM * DDIM];  // packed (tf32_hi, tf32_lo) of softmax(w), [k][d]
__device__ float  g_nT[KDIM * DDIM];  // min-max normalized w columns, transposed
__device__ int    g_e[NROWS];         // argmax k (bits0..5) | neg-sign (bit6)

// ---------------------------------------------------------------------------
// helpers
// ---------------------------------------------------------------------------
__device__ __forceinline__ unsigned smem_u32(const void* p) {
    return (unsigned)__cvta_generic_to_shared(p);
}
__device__ __forceinline__ void cp16(void* dst, const void* src) {
    asm volatile("cp.async.cg.shared.global [%0], [%1], 16;\n"
                 :: "r"(smem_u32(dst)), "l"(src));
}
__device__ __forceinline__ unsigned f2tf(float f) {   // round-to-nearest tf32
    unsigned u;
    asm("cvt.rna.tf32.f32 %0, %1;" : "=r"(u) : "f"(f));
    return u;
}
// m16n8k8 tf32 mma, D += A*B (baseline PTX, sm_80+)
__device__ __forceinline__ void mma8(float* d, const unsigned* a, const unsigned* b) {
    asm volatile(
        "mma.sync.aligned.m16n8k8.row.col.f32.tf32.tf32.f32 "
        "{%0,%1,%2,%3}, {%4,%5,%6,%7}, {%8,%9}, {%0,%1,%2,%3};"
        : "+f"(d[0]), "+f"(d[1]), "+f"(d[2]), "+f"(d[3])
        : "r"(a[0]), "r"(a[1]), "r"(a[2]), "r"(a[3]), "r"(b[0]), "r"(b[1]));
}

// ---------------------------------------------------------------------------
// Kernel 1a: softmax of w rows (over K) in fp64; write packed tf32 hi/lo,
// transposed [k][d]. One warp per d-row (2 k per lane).
// ---------------------------------------------------------------------------
__global__ void prep_softmax(const float* __restrict__ w) {
    int gw = (blockIdx.x * blockDim.x + threadIdx.x) >> 5;
    if (gw >= DDIM) return;
    int lane = threadIdx.x & 31;
    float w0 = w[gw * KDIM + lane];
    float w1 = w[gw * KDIM + lane + 32];
    float m = fmaxf(w0, w1);
#pragma unroll
    for (int off = 16; off; off >>= 1)
        m = fmaxf(m, __shfl_xor_sync(0xffffffffu, m, off));
    double e0 = exp((double)(w0 - m));
    double e1 = exp((double)(w1 - m));
    double s = e0 + e1;
#pragma unroll
    for (int off = 16; off; off >>= 1)
        s += __shfl_xor_sync(0xffffffffu, s, off);
    float p0 = (float)(e0 / s), p1 = (float)(e1 / s);
    float h0 = __uint_as_float(f2tf(p0));
    float h1 = __uint_as_float(f2tf(p1));
    g_pP[lane * DDIM + gw]        = make_float2(h0, __uint_as_float(f2tf(p0 - h0)));
    g_pP[(lane + 32) * DDIM + gw] = make_float2(h1, __uint_as_float(f2tf(p1 - h1)));
}

// ---------------------------------------------------------------------------
// Kernel 1b: per-column min/max of w -> normalized columns in g_nT[k][d].
// ---------------------------------------------------------------------------
__global__ void prep_norm(const float* __restrict__ w) {
    const int k = blockIdx.x;
    const int tid = threadIdx.x;
    float mn = 3.402823466e38f, mx = -3.402823466e38f;
    for (int d = tid; d < DDIM; d += 256) {
        float v = w[d * KDIM + k];
        mn = fminf(mn, v);
        mx = fmaxf(mx, v);
    }
    __shared__ float smn[256], smx[256];
    smn[tid] = mn; smx[tid] = mx;
    __syncthreads();
    for (int s = 128; s; s >>= 1) {
        if (tid < s) {
            smn[tid] = fminf(smn[tid], smn[tid + s]);
            smx[tid] = fmaxf(smx[tid], smx[tid + s]);
        }
        __syncthreads();
    }
    mn = smn[0]; mx = smx[0];
    float inv = 1.f / (mx - mn);
    for (int d = tid; d < DDIM; d += 256)
        g_nT[k * DDIM + d] = (w[d * KDIM + k] - mn) * inv;
}

// ---------------------------------------------------------------------------
// Kernel 2: scores = x @ p via mma.sync 3xTF32; per-row argmax/sign -> g_e.
// 128 CTAs x (128 tok, 64 k). 4 warps, each 32 tok x 64 k (acc 64 fp32).
// D in 64 chunks of 32; 4-stage cp.async pipeline, 1 sync per chunk.
// ---------------------------------------------------------------------------
#define XSTRIDE 36            // floats per x row (36 = 4 mod 32 -> conflict-free)
#define XBYTES  (128 * XSTRIDE * 4)        // 18432
#define PSTRIDE 36            // float2 per p row (conflict-free LDS.64)
#define PBYTES  (KDIM * PSTRIDE * 8)       // 18432
#define STG     (XBYTES + PBYTES)          // 36864
#define SMEM_SZ (4 * STG)                  // 147456

__global__ __launch_bounds__(128, 1) void score_kernel(const float* __restrict__ x) {
    extern __shared__ char sm[];
    const int tid = threadIdx.x;
    const int wid = tid >> 5, lane = tid & 31;
    const int lq = lane >> 2;             // 0..7
    const int lr = lane & 3;              // 0..3
    const float* xg = x + (size_t)blockIdx.x * 128 * DDIM;

    float acc[2][8][4];
#pragma unroll
    for (int mt = 0; mt < 2; mt++)
#pragma unroll
        for (int nt = 0; nt < 8; nt++)
#pragma unroll
            for (int e = 0; e < 4; e++) acc[mt][nt][e] = 0.f;

    auto prefetch = [&](int c) {
        char* base = sm + (size_t)(c & 3) * STG;
#pragma unroll
        for (int i = 0; i < 8; i++) {               // x raw: 128 rows x 32 floats
            int v = tid + 128 * i;
            int row = v >> 3, s = v & 7;
            cp16(base + row * (XSTRIDE * 4) + s * 16,
                 xg + (size_t)row * DDIM + c * 32 + s * 4);
        }
#pragma unroll
        for (int i = 0; i < 8; i++) {               // p packed: 64 rows x 32 float2
            int v = tid + 128 * i;
            int row = v >> 4, s = v & 15;
            cp16(base + XBYTES + row * (PSTRIDE * 8) + s * 16,
                 (const char*)g_pP + (size_t)row * (DDIM * 8) + c * 256 + s * 16);
        }
        asm volatile("cp.async.commit_group;\n");
    };

    prefetch(0); prefetch(1); prefetch(2);

#pragma unroll 1
    for (int c = 0; c < 64; ++c) {
        if (c < 62)       asm volatile("cp.async.wait_group 2;\n");
        else if (c == 62) asm volatile("cp.async.wait_group 1;\n");
        else              asm volatile("cp.async.wait_group 0;\n");
        __syncthreads();   // stage c visible; all threads done reading stage (c-1)%4
        if (c + 3 < 64) prefetch(c + 3);

        const char* base = sm + (size_t)(c & 3) * STG;
        const float*  xs = (const float*)base;
        const float2* ps = (const float2*)(base + XBYTES);

#pragma unroll
        for (int s8 = 0; s8 < 4; ++s8) {
            // A fragments: raw x -> (hi, lo) tf32 split in registers.
            unsigned ah[2][4], al[2][4];
#pragma unroll
            for (int mt = 0; mt < 2; mt++) {
#pragma unroll
                for (int e = 0; e < 4; e++) {
                    int r = wid * 32 + mt * 16 + lq + (e & 1) * 8;
                    int d = s8 * 8 + lr + (e >> 1) * 4;
                    float raw = xs[r * XSTRIDE + d];
                    unsigned h = f2tf(raw);
                    ah[mt][e] = h;
                    al[mt][e] = f2tf(raw - __uint_as_float(h));
                }
            }
            // B fragments: packed (hi, lo) from one LDS.64 each.
            unsigned bh[8][2], bl[8][2];
#pragma unroll
            for (int nt = 0; nt < 8; nt++) {
                int k = nt * 8 + lq;
                float2 f0 = ps[k * PSTRIDE + s8 * 8 + lr];
                float2 f1 = ps[k * PSTRIDE + s8 * 8 + lr + 4];
                bh[nt][0] = __float_as_uint(f0.x);
                bh[nt][1] = __float_as_uint(f1.x);
                bl[nt][0] = __float_as_uint(f0.y);
                bl[nt][1] = __float_as_uint(f1.y);
            }
#pragma unroll
            for (int mt = 0; mt < 2; mt++)
#pragma unroll
                for (int nt = 0; nt < 8; nt++) {
                    mma8(acc[mt][nt], ah[mt], bh[nt]);   // hi*hi
                    mma8(acc[mt][nt], ah[mt], bl[nt]);   // hi*lo
                    mma8(acc[mt][nt], al[mt], bh[nt]);   // lo*hi
                }
        }
    }

    // Epilogue: per-row argmax over 64 k. Thread covers rows
    // {wid*32 + mt*16 + h*8 + lq}, cols {nt*8 + 2*lr + j}.
#pragma unroll
    for (int mt = 0; mt < 2; mt++) {
#pragma unroll
        for (int h = 0; h < 2; h++) {
            float bv = -3.402823466e38f; int bk = 0;
#pragma unroll
            for (int nt = 0; nt < 8; nt++) {
#pragma unroll
                for (int j = 0; j < 2; j++) {
                    float v = acc[mt][nt][h * 2 + j];
                    int k = nt * 8 + 2 * lr + j;     // ascending scan order
                    if (v > bv) { bv = v; bk = k; }
                }
            }
            // combine across the 4 lanes of the quad (same lq)
#pragma unroll
            for (int off = 1; off <= 2; off <<= 1) {
                float ov = __shfl_xor_sync(0xffffffffu, bv, off);
                int   ok = __shfl_xor_sync(0xffffffffu, bk, off);
                if (ov > bv || (ov == bv && ok < bk)) { bv = ov; bk = ok; }
            }
            if (lr == 0) {
                int row = blockIdx.x * 128 + wid * 32 + mt * 16 + h * 8 + lq;
                g_e[row] = bk | (bv < 0.f ? 64 : 0);
            }
        }
    }
}

// ---------------------------------------------------------------------------
// Kernel 3: out[row] = x + x*W, W = nT[k*] or 1-nT[k*] from row-1's (k*,sign).
// ---------------------------------------------------------------------------
__global__ __launch_bounds__(256) void out_kernel(const float* __restrict__ x,
                                                  float* __restrict__ out) {
    const long row = blockIdx.x;
    const int tid = threadIdx.x;
    const float4* xr = reinterpret_cast<const float4*>(x + row * DDIM);
    float4* orow = reinterpret_cast<float4*>(out + row * DDIM);
    if ((row & 2047) == 0) {          // t == 0 -> W = 0
        orow[tid] = xr[tid];
        orow[tid + 256] = xr[tid + 256];
        return;
    }
    const int e = g_e[row - 1];
    const float4* nr = reinterpret_cast<const float4*>(g_nT + (long)(e & 63) * DDIM);
    const bool neg = (e & 64) != 0;
#pragma unroll
    for (int it = 0; it < 2; ++it) {
        int i = tid + 256 * it;
        float4 xv = xr[i];
        float4 nv = nr[i];
        float wx = neg ? 1.f - nv.x : nv.x;
        float wy = neg ? 1.f - nv.y : nv.y;
        float wz = neg ? 1.f - nv.z : nv.z;
        float ww = neg ? 1.f - nv.w : nv.w;
        float4 o;
        o.x = fmaf(xv.x, wx, xv.x);
        o.y = fmaf(xv.y, wy, xv.y);
        o.z = fmaf(xv.z, wz, xv.z);
        o.w = fmaf(xv.w, ww, xv.w);
        orow[i] = o;
    }
}

// ---------------------------------------------------------------------------
extern "C" void kernel_launch(void* const* d_in, const int* in_sizes, int n_in,
                              void* d_out, int out_size) {
    const float* x = (const float*)d_in[0];
    const float* w = (const float*)d_in[1];
    if (n_in >= 2 && in_sizes[0] < in_sizes[1]) {
        const float* t = x; x = w; w = t;
    }
    static bool attr_set = false;
    if (!attr_set) {
        cudaFuncSetAttribute(score_kernel,
                             cudaFuncAttributeMaxDynamicSharedMemorySize, SMEM_SZ);
        attr_set = true;
    }
    prep_softmax<<<DDIM / 8, 256>>>(w);
    prep_norm<<<KDIM, 256>>>(w);
    score_kernel<<<NROWS / 128, 128, SMEM_SZ>>>(x);
    out_kernel<<<NROWS, 256>>>(x, (float*)d_out);
}

// round 9
// speedup vs baseline: 1.6821x; 1.4049x over previous
#include <cuda_runtime.h>
#include <cuda_fp16.h>
#include <cstdint>
#include <math.h>

// Problem constants: B=8, T=2048, D=2048, K=64
#define NROWS 16384
#define DDIM  2048
#define KDIM  64

// Scratch (allocation-free __device__ globals)
// g_pP[k][d/2] = { f16x2(ph[d], ph[d+1]),  f16x2(pl[d]*1024, pl[d+1]*1024) }
__device__ uint2 g_pP[KDIM * (DDIM / 2)];
__device__ float g_nT[KDIM * DDIM];   // min-max normalized w columns, transposed
__device__ int   g_e[NROWS];          // argmax k (bits0..5) | neg-sign (bit6)

// ---------------------------------------------------------------------------
// helpers
// ---------------------------------------------------------------------------
__device__ __forceinline__ unsigned smem_u32(const void* p) {
    return (unsigned)__cvta_generic_to_shared(p);
}
__device__ __forceinline__ void cp16(void* dst, const void* src) {
    asm volatile("cp.async.cg.shared.global [%0], [%1], 16;\n"
                 :: "r"(smem_u32(dst)), "l"(src));
}
// m16n8k16 fp16 mma, fp32 acc, D += A*B (baseline PTX, sm_80+)
__device__ __forceinline__ void mma16(float* d, const unsigned* a, const unsigned* b) {
    asm volatile(
        "mma.sync.aligned.m16n8k16.row.col.f32.f16.f16.f32 "
        "{%0,%1,%2,%3}, {%4,%5,%6,%7}, {%8,%9}, {%0,%1,%2,%3};"
        : "+f"(d[0]), "+f"(d[1]), "+f"(d[2]), "+f"(d[3])
        : "r"(a[0]), "r"(a[1]), "r"(a[2]), "r"(a[3]), "r"(b[0]), "r"(b[1]));
}

// ---------------------------------------------------------------------------
// Kernel 1a: softmax of w rows (over K) in fp64; write packed fp16 hi/lo
// pairs transposed: g_pP[k][d/2]. One warp per d-PAIR (2 d-rows, 2 k/lane).
// ---------------------------------------------------------------------------
__global__ void prep_softmax(const float* __restrict__ w) {
    int gw = (blockIdx.x * blockDim.x + threadIdx.x) >> 5;   // d-pair id
    if (gw >= DDIM / 2) return;
    int lane = threadIdx.x & 31;
    int d0 = gw * 2, d1 = d0 + 1;
    float a0 = w[d0 * KDIM + lane], a1 = w[d0 * KDIM + lane + 32];
    float b0 = w[d1 * KDIM + lane], b1 = w[d1 * KDIM + lane + 32];
    float m0 = fmaxf(a0, a1), m1 = fmaxf(b0, b1);
#pragma unroll
    for (int off = 16; off; off >>= 1) {
        m0 = fmaxf(m0, __shfl_xor_sync(0xffffffffu, m0, off));
        m1 = fmaxf(m1, __shfl_xor_sync(0xffffffffu, m1, off));
    }
    double ea0 = exp((double)(a0 - m0)), ea1 = exp((double)(a1 - m0));
    double eb0 = exp((double)(b0 - m1)), eb1 = exp((double)(b1 - m1));
    double s0 = ea0 + ea1, s1 = eb0 + eb1;
#pragma unroll
    for (int off = 16; off; off >>= 1) {
        s0 += __shfl_xor_sync(0xffffffffu, s0, off);
        s1 += __shfl_xor_sync(0xffffffffu, s1, off);
    }
    // k = lane:   p(d0)=ea0/s0, p(d1)=eb0/s1 ; k = lane+32: ea1/s0, eb1/s1
#pragma unroll
    for (int half = 0; half < 2; half++) {
        int k = lane + 32 * half;
        float p0 = (float)((half ? ea1 : ea0) / s0);
        float p1 = (float)((half ? eb1 : eb0) / s1);
        __half h0 = __float2half_rn(p0);
        __half h1 = __float2half_rn(p1);
        float l0 = (p0 - __half2float(h0)) * 1024.f;
        float l1 = (p1 - __half2float(h1)) * 1024.f;
        __half2 hp = __halves2half2(h0, h1);            // low = d0
        __half2 lp = __floats2half2_rn(l0, l1);         // low = d0
        uint2 v;
        v.x = *reinterpret_cast<unsigned*>(&hp);
        v.y = *reinterpret_cast<unsigned*>(&lp);
        g_pP[k * (DDIM / 2) + gw] = v;
    }
}

// ---------------------------------------------------------------------------
// Kernel 1b: per-column min/max of w -> normalized columns in g_nT[k][d].
// ---------------------------------------------------------------------------
__global__ void prep_norm(const float* __restrict__ w) {
    const int k = blockIdx.x;
    const int tid = threadIdx.x;
    float mn = 3.402823466e38f, mx = -3.402823466e38f;
    for (int d = tid; d < DDIM; d += 256) {
        float v = w[d * KDIM + k];
        mn = fminf(mn, v);
        mx = fmaxf(mx, v);
    }
    __shared__ float smn[256], smx[256];
    smn[tid] = mn; smx[tid] = mx;
    __syncthreads();
    for (int s = 128; s; s >>= 1) {
        if (tid < s) {
            smn[tid] = fminf(smn[tid], smn[tid + s]);
            smx[tid] = fmaxf(smx[tid], smx[tid + s]);
        }
        __syncthreads();
    }
    mn = smn[0]; mx = smx[0];
    float inv = 1.f / (mx - mn);
    for (int d = tid; d < DDIM; d += 256)
        g_nT[k * DDIM + d] = (w[d * KDIM + k] - mn) * inv;
}

// ---------------------------------------------------------------------------
// Kernel 2: scores = x @ p via fp16 m16n8k16 3-term split (scaled lo-acc).
// 128 CTAs x (128 tok, 64 k). 4 warps. D in 64 chunks of 32 dims
// (2 k16 steps each). 4-stage cp.async pipeline, 1 sync per chunk.
// ---------------------------------------------------------------------------
#define XSTR 40                        // floats per x smem row (bank 8*lq)
#define XB   (128 * XSTR * 4)          // 20480
#define PSTR 20                        // uint2 per p smem row (bank 8*lq)
#define PB   (KDIM * PSTR * 8)         // 10240
#define STG  (XB + PB)                 // 30720
#define SMEM_SZ (4 * STG)              // 122880

__global__ __launch_bounds__(128, 1) void score_kernel(const float* __restrict__ x) {
    extern __shared__ char sm[];
    const int tid = threadIdx.x;
    const int wid = tid >> 5, lane = tid & 31;
    const int lq = lane >> 2;          // 0..7
    const int lr = lane & 3;           // 0..3
    const float* xg = x + (size_t)blockIdx.x * 128 * DDIM;

    float accH[2][8][4], accL[2][8][4];
#pragma unroll
    for (int mt = 0; mt < 2; mt++)
#pragma unroll
        for (int nt = 0; nt < 8; nt++)
#pragma unroll
            for (int e = 0; e < 4; e++) { accH[mt][nt][e] = 0.f; accL[mt][nt][e] = 0.f; }

    auto prefetch = [&](int c) {
        char* base = sm + (size_t)(c & 3) * STG;
#pragma unroll
        for (int i = 0; i < 8; i++) {               // x: 128 rows x 32 floats
            int v = tid + 128 * i;
            int row = v >> 3, s = v & 7;
            cp16(base + row * (XSTR * 4) + s * 16,
                 xg + (size_t)row * DDIM + c * 32 + s * 4);
        }
#pragma unroll
        for (int i = 0; i < 4; i++) {               // p: 64 rows x 16 uint2 (128B)
            int v = tid + 128 * i;
            int row = v >> 3, s = v & 7;
            cp16(base + XB + row * (PSTR * 8) + s * 16,
                 (const char*)g_pP + (size_t)row * (DDIM * 4) + c * 128 + s * 16);
        }
        asm volatile("cp.async.commit_group;\n");
    };

    prefetch(0); prefetch(1); prefetch(2);

#pragma unroll 1
    for (int c = 0; c < 64; ++c) {
        if (c < 62)       asm volatile("cp.async.wait_group 2;\n");
        else if (c == 62) asm volatile("cp.async.wait_group 1;\n");
        else              asm volatile("cp.async.wait_group 0;\n");
        __syncthreads();
        if (c + 3 < 64) prefetch(c + 3);

        const char* base = sm + (size_t)(c & 3) * STG;
        const float* xs = (const float*)base;
        const uint2* ps = (const uint2*)(base + XB);

#pragma unroll
        for (int s = 0; s < 2; ++s) {               // two k16 steps per chunk
            // A fragments: f32 pair -> fp16 hi + scaled-lo in registers
            unsigned ah[2][4], al[2][4];
#pragma unroll
            for (int mt = 0; mt < 2; mt++) {
#pragma unroll
                for (int pr = 0; pr < 4; pr++) {
                    int row = wid * 32 + mt * 16 + lq + (pr & 1) * 8;
                    int dof = 16 * s + 2 * lr + (pr >> 1) * 8;
                    float2 f = *reinterpret_cast<const float2*>(xs + row * XSTR + dof);
                    __half2 h2 = __floats2half2_rn(f.x, f.y);
                    float2 bk = __half22float2(h2);
                    __half2 l2 = __floats2half2_rn((f.x - bk.x) * 1024.f,
                                                   (f.y - bk.y) * 1024.f);
                    ah[mt][pr] = *reinterpret_cast<unsigned*>(&h2);
                    al[mt][pr] = *reinterpret_cast<unsigned*>(&l2);
                }
            }
            // B fragments: one LDS.64 per (k, d-pair) yields {hi, lo}
            unsigned bh[8][2], bl[8][2];
#pragma unroll
            for (int nt = 0; nt < 8; nt++) {
                int k = nt * 8 + lq;
                uint2 v0 = ps[k * PSTR + 8 * s + lr];
                uint2 v1 = ps[k * PSTR + 8 * s + lr + 4];
                bh[nt][0] = v0.x; bl[nt][0] = v0.y;
                bh[nt][1] = v1.x; bl[nt][1] = v1.y;
            }
#pragma unroll
            for (int mt = 0; mt < 2; mt++)
#pragma unroll
                for (int nt = 0; nt < 8; nt++) {
                    mma16(accH[mt][nt], ah[mt], bh[nt]);   // hi*hi
                    mma16(accL[mt][nt], ah[mt], bl[nt]);   // hi*lo'
                    mma16(accL[mt][nt], al[mt], bh[nt]);   // lo'*hi
                }
        }
    }

    // Epilogue: score = accH + accL/1024; per-row argmax over 64 k.
#pragma unroll
    for (int mt = 0; mt < 2; mt++) {
#pragma unroll
        for (int h = 0; h < 2; h++) {
            float bv = -3.402823466e38f; int bk = 0;
#pragma unroll
            for (int nt = 0; nt < 8; nt++) {
#pragma unroll
                for (int j = 0; j < 2; j++) {
                    float v = accH[mt][nt][h * 2 + j]
                            + accL[mt][nt][h * 2 + j] * 9.765625e-4f;
                    int k = nt * 8 + 2 * lr + j;     // ascending scan order
                    if (v > bv) { bv = v; bk = k; }
                }
            }
#pragma unroll
            for (int off = 1; off <= 2; off <<= 1) {
                float ov = __shfl_xor_sync(0xffffffffu, bv, off);
                int   ok = __shfl_xor_sync(0xffffffffu, bk, off);
                if (ov > bv || (ov == bv && ok < bk)) { bv = ov; bk = ok; }
            }
            if (lr == 0) {
                int row = blockIdx.x * 128 + wid * 32 + mt * 16 + h * 8 + lq;
                g_e[row] = bk | (bv < 0.f ? 64 : 0);
            }
        }
    }
}

// ---------------------------------------------------------------------------
// Kernel 3: out = x + x*W. 4 rows per CTA, all loads front-batched (high MLP).
// ---------------------------------------------------------------------------
__global__ __launch_bounds__(256) void out_kernel(const float* __restrict__ x,
                                                  float* __restrict__ out) {
    const int tid = threadIdx.x;
    const long base = (long)blockIdx.x * 4;
    const float4* xr = reinterpret_cast<const float4*>(x + base * DDIM);
    float4* orow = reinterpret_cast<float4*>(out + base * DDIM);

    float4 xv[8];
#pragma unroll
    for (int r = 0; r < 4; r++) {
        xv[2 * r]     = xr[r * 512 + tid];
        xv[2 * r + 1] = xr[r * 512 + tid + 256];
    }
    int ev[4];
#pragma unroll
    for (int r = 0; r < 4; r++) {
        long row = base + r;
        ev[r] = ((row & 2047) == 0) ? -1 : g_e[row - 1];
    }
    float4 nv[8];
#pragma unroll
    for (int r = 0; r < 4; r++) {           // branchless gather (idx 0 if t==0)
        const float4* nr = reinterpret_cast<const float4*>(
            g_nT + (long)(ev[r] < 0 ? 0 : (ev[r] & 63)) * DDIM);
        nv[2 * r]     = nr[tid];
        nv[2 * r + 1] = nr[tid + 256];
    }
#pragma unroll
    for (int r = 0; r < 4; r++) {
        const bool zero = ev[r] < 0;
        const bool neg  = (ev[r] & 64) != 0;
#pragma unroll
        for (int half = 0; half < 2; half++) {
            float4 xq = xv[2 * r + half];
            float4 nq = nv[2 * r + half];
            float wx = zero ? 0.f : (neg ? 1.f - nq.x : nq.x);
            float wy = zero ? 0.f : (neg ? 1.f - nq.y : nq.y);
            float wz = zero ? 0.f : (neg ? 1.f - nq.z : nq.z);
            float ww = zero ? 0.f : (neg ? 1.f - nq.w : nq.w);
            float4 o;
            o.x = fmaf(xq.x, wx, xq.x);
            o.y = fmaf(xq.y, wy, xq.y);
            o.z = fmaf(xq.z, wz, xq.z);
            o.w = fmaf(xq.w, ww, xq.w);
            orow[r * 512 + half * 256 + tid] = o;
        }
    }
}

// ---------------------------------------------------------------------------
extern "C" void kernel_launch(void* const* d_in, const int* in_sizes, int n_in,
                              void* d_out, int out_size) {
    const float* x = (const float*)d_in[0];
    const float* w = (const float*)d_in[1];
    if (n_in >= 2 && in_sizes[0] < in_sizes[1]) {
        const float* t = x; x = w; w = t;
    }
    static bool attr_set = false;
    if (!attr_set) {
        cudaFuncSetAttribute(score_kernel,
                             cudaFuncAttributeMaxDynamicSharedMemorySize, SMEM_SZ);
        attr_set = true;
    }
    prep_softmax<<<128, 256>>>(w);          // 1024 warps = DDIM/2 d-pairs
    prep_norm<<<KDIM, 256>>>(w);
    score_kernel<<<NROWS / 128, 128, SMEM_SZ>>>(x);
    out_kernel<<<NROWS / 4, 256>>>(x, (float*)d_out);
}